// round 1
// baseline (speedup 1.0000x reference)
#include <cuda_runtime.h>
#include <math.h>

#define BATCH 16
#define NCLS  20
#define NGT   64
#define N3    16384
#define N4    4096
#define N5    1024
#define NTOT  (N3 + N4 + N5)     // 21504
#define TOPK  1000
#define MAXDET 100
#define SCORE_THR 0.3f
#define IOU_THR   0.5f

// ---------------- scratch (device globals; no allocations allowed) ----------
__device__ float  g_scores[BATCH * NTOT];
__device__ float4 g_boxes [BATCH * NTOT];
__device__ int    g_cls   [BATCH * NTOT];

__device__ __forceinline__ float sigmoidf_(float x) {
    if (x >= 0.f) return 1.f / (1.f + expf(-x));
    float e = expf(x);
    return e / (1.f + e);
}

// ---------------- kernel 1: GT matching + regression/centerness targets -----
__global__ void k_targets(const float* __restrict__ l3, const float* __restrict__ l4,
                          const float* __restrict__ l5, const float* __restrict__ gt,
                          float* __restrict__ od, float* __restrict__ oc)
{
    int b = blockIdx.y;
    int i = blockIdx.x * blockDim.x + threadIdx.x;
    __shared__ float sgt[NGT * 5];
    for (int t = threadIdx.x; t < NGT * 5; t += blockDim.x) sgt[t] = gt[b * NGT * 5 + t];
    __syncthreads();
    if (i >= NTOT) return;

    float xc, yc, lower, upper, stride;
    if (i < N3)            { xc = l3[2*i];           yc = l3[2*i+1];           lower = 0.f;   upper = 64.f;     stride = 8.f;  }
    else if (i < N3 + N4)  { int j = i - N3;         xc = l4[2*j]; yc = l4[2*j+1]; lower = 64.f;  upper = 128.f;    stride = 16.f; }
    else                   { int j = i - N3 - N4;    xc = l5[2*j]; yc = l5[2*j+1]; lower = 128.f; upper = INFINITY; stride = 32.f; }

    float bestq = 0.f;
    int   besti = -1;
    #pragma unroll 4
    for (int m = 0; m < NGT; m++) {
        float x0 = sgt[5*m+0], y0 = sgt[5*m+1], x1 = sgt[5*m+2], y1 = sgt[5*m+3];
        float l = xc - x0, t = yc - y0, r = x1 - xc, bm = y1 - yc;
        float mn = fminf(fminf(l, t), fminf(r, bm));
        float mx = fmaxf(fmaxf(l, t), fmaxf(r, bm));
        float area = (x1 - x0) * (y1 - y0);
        bool ok = (mn > 0.f) && (mx > lower) && (mx < upper);
        float q = ok ? (1e8f - area) : 0.f;
        if (q > bestq) { bestq = q; besti = m; }   // strict > : argmax-first semantics
    }
    if (bestq < 1e-5f) besti = -1;

    float d0, d1, d2, d3, ctr;
    if (besti < 0) {
        d0 = d1 = d2 = d3 = -1.f; ctr = -1.f;
    } else {
        float x0 = sgt[5*besti+0], y0 = sgt[5*besti+1], x1 = sgt[5*besti+2], y1 = sgt[5*besti+3];
        d0 = (xc - x0) / stride;
        d1 = (yc - y0) / stride;
        d2 = (x1 - xc) / stride;
        d3 = (y1 - yc) / stride;
        float num = fminf(d0, d2) * fminf(d1, d3);
        float den = fmaxf(d0, d2) * fmaxf(d1, d3);
        ctr = sqrtf(num / den);
    }
    size_t base = (size_t)(b * NTOT + i);
    od[base*4+0] = d0; od[base*4+1] = d1; od[base*4+2] = d2; od[base*4+3] = d3;
    oc[base] = ctr;
}

// ---------------- kernel 2: class-max score + box decode --------------------
__global__ void k_score(const float* __restrict__ l3, const float* __restrict__ l4, const float* __restrict__ l5,
                        const float* __restrict__ c3, const float* __restrict__ c4, const float* __restrict__ c5,
                        const float* __restrict__ r3, const float* __restrict__ r4, const float* __restrict__ r5,
                        const float* __restrict__ t3, const float* __restrict__ t4, const float* __restrict__ t5)
{
    int b = blockIdx.y;
    int i = blockIdx.x * blockDim.x + threadIdx.x;
    if (i >= NTOT) return;

    const float *locs, *cls, *reg, *ctr;
    int j, n; float stride;
    if (i < N3)           { j = i;          n = N3; locs = l3; cls = c3; reg = r3; ctr = t3; stride = 8.f;  }
    else if (i < N3 + N4) { j = i - N3;     n = N4; locs = l4; cls = c4; reg = r4; ctr = t4; stride = 16.f; }
    else                  { j = i - N3 - N4;n = N5; locs = l5; cls = c5; reg = r5; ctr = t5; stride = 32.f; }

    float xc = locs[2*j], yc = locs[2*j+1];
    const float* cp = cls + ((size_t)b * n + j) * NCLS;
    float best = cp[0]; int bc = 0;
    #pragma unroll
    for (int c = 1; c < NCLS; c++) { float v = cp[c]; if (v > best) { best = v; bc = c; } }

    float sc = sqrtf(sigmoidf_(best) * sigmoidf_(ctr[(size_t)b * n + j]));

    const float* rp = reg + ((size_t)b * n + j) * 4;
    float d0 = fmaxf(rp[0], 0.f) * stride;
    float d1 = fmaxf(rp[1], 0.f) * stride;
    float d2 = fmaxf(rp[2], 0.f) * stride;
    float d3 = fmaxf(rp[3], 0.f) * stride;
    float4 bx = make_float4(xc - d0, yc - d1, xc + d2, yc + d3);

    int o = b * NTOT + i;
    g_scores[o] = sc;
    g_boxes[o]  = bx;
    g_cls[o]    = bc;
}

// ---------------- kernel 3: per-batch exact top-1000 + greedy NMS -----------
__device__ __forceinline__ unsigned int fenc(float f) {
    unsigned int u = __float_as_uint(f);
    return (u & 0x80000000u) ? ~u : (u | 0x80000000u);
}
__device__ __forceinline__ float fdec(unsigned int e) {
    return (e & 0x80000000u) ? __uint_as_float(e & 0x7FFFFFFFu) : __uint_as_float(~e);
}

__global__ __launch_bounds__(1024) void k_select(float* __restrict__ dets)
{
    __shared__ float4              nbox[TOPK];      // 16B-aligned first
    __shared__ unsigned long long  keys[2048];
    __shared__ unsigned int        hist[2048];
    __shared__ float               area_s[TOPK];
    __shared__ unsigned char       active[TOPK];
    __shared__ unsigned char       keepf[TOPK];
    __shared__ unsigned int        sCnt, sThr, sMaxU;
    __shared__ int                 sB1, sB2, sPick;

    const int b   = blockIdx.x;
    const int tid = threadIdx.x;
    const int NT  = 1024;
    const float* sc = g_scores + b * NTOT;

    // ---- pass 1: histogram of float bits [31:21] ----
    for (int k = tid; k < 2048; k += NT) hist[k] = 0;
    __syncthreads();
    for (int k = tid; k < NTOT; k += NT)
        atomicAdd(&hist[__float_as_uint(sc[k]) >> 21], 1u);
    __syncthreads();
    if (tid == 0) {
        unsigned int cum = 0; int b1 = 0;
        for (int k = 2047; k >= 0; k--) {
            if (cum + hist[k] >= TOPK) { b1 = k; break; }
            cum += hist[k];
        }
        sB1 = b1; sCnt = cum;
    }
    __syncthreads();
    const unsigned int b1 = (unsigned int)sB1;
    const unsigned int above1 = sCnt;

    // ---- pass 2: bits [20:10] within bin b1 ----
    for (int k = tid; k < 2048; k += NT) hist[k] = 0;
    __syncthreads();
    for (int k = tid; k < NTOT; k += NT) {
        unsigned int bits = __float_as_uint(sc[k]);
        if ((bits >> 21) == b1) atomicAdd(&hist[(bits >> 10) & 2047u], 1u);
    }
    __syncthreads();
    if (tid == 0) {
        unsigned int cum = above1; int b2 = 0;
        for (int k = 2047; k >= 0; k--) {
            if (cum + hist[k] >= TOPK) { b2 = k; break; }
            cum += hist[k];
        }
        sB2 = b2; sCnt = cum;
    }
    __syncthreads();
    const unsigned int b2 = (unsigned int)sB2;
    const unsigned int above2 = sCnt;
    const unsigned int pref21 = (b1 << 11) | b2;

    // ---- pass 3: bits [9:0] within (b1,b2) -> exact 1000th-key threshold ----
    for (int k = tid; k < 1024; k += NT) hist[k] = 0;
    __syncthreads();
    for (int k = tid; k < NTOT; k += NT) {
        unsigned int bits = __float_as_uint(sc[k]);
        if ((bits >> 10) == pref21) atomicAdd(&hist[bits & 1023u], 1u);
    }
    __syncthreads();
    if (tid == 0) {
        unsigned int cum = above2; int b3 = 0;
        for (int k = 1023; k >= 0; k--) {
            if (cum + hist[k] >= TOPK) { b3 = k; break; }
            cum += hist[k];
        }
        sThr = (b1 << 21) | (b2 << 10) | (unsigned int)b3;
        sCnt = 0;
        sMaxU = 0;
    }
    __syncthreads();
    const unsigned int thr = sThr;

    // ---- compaction: all elements with bits >= thr (>= 1000, ~1000 + ties) ----
    for (int k = tid; k < NTOT; k += NT) {
        unsigned int bits = __float_as_uint(sc[k]);
        if (bits >= thr) {
            unsigned int pos = atomicAdd(&sCnt, 1u);
            if (pos < 2048)
                keys[pos] = ((unsigned long long)bits << 32) | (unsigned long long)(0xFFFFFFFFu - (unsigned int)k);
        }
    }
    __syncthreads();
    const unsigned int S = min(sCnt, 2048u);
    for (int k = tid; k < 2048; k += NT)
        if ((unsigned int)k >= S) keys[k] = 0ull;
    __syncthreads();

    // ---- bitonic sort ascending (rank r lives at keys[2047-r]) ----
    // key = (score_bits << 32) | ~index  => score desc, index asc == jax top_k order
    for (unsigned int ksz = 2; ksz <= 2048; ksz <<= 1) {
        for (unsigned int j = ksz >> 1; j > 0; j >>= 1) {
            __syncthreads();
            for (unsigned int i = tid; i < 2048; i += NT) {
                unsigned int ixj = i ^ j;
                if (ixj > i) {
                    unsigned long long a = keys[i], c = keys[ixj];
                    bool up = ((i & ksz) == 0);
                    if (up ? (a > c) : (a < c)) { keys[i] = c; keys[ixj] = a; }
                }
            }
        }
    }
    __syncthreads();

    // ---- gather top-1000; compute max_coord over valid rows ----
    for (int r = tid; r < TOPK; r += NT) {
        unsigned long long key = keys[2047 - r];
        float s = __uint_as_float((unsigned int)(key >> 32));
        unsigned int idx = 0xFFFFFFFFu - (unsigned int)key;
        float4 bx = g_boxes[b * NTOT + idx];
        bool valid = s > SCORE_THR;
        active[r] = valid ? 1 : 0;
        keepf[r] = 0;
        float m = valid ? fmaxf(fmaxf(bx.x, bx.y), fmaxf(bx.z, bx.w)) : 0.f;
        atomicMax(&sMaxU, fenc(m));
    }
    __syncthreads();
    const float offmul = fdec(sMaxU) + 1.0f;

    // ---- build class-offset boxes + areas (areas on OFFSET boxes, as ref) ----
    for (int r = tid; r < TOPK; r += NT) {
        unsigned long long key = keys[2047 - r];
        unsigned int idx = 0xFFFFFFFFu - (unsigned int)key;
        float4 bx = g_boxes[b * NTOT + idx];
        float off = (float)g_cls[b * NTOT + idx] * offmul;
        float4 nb = make_float4(bx.x + off, bx.y + off, bx.z + off, bx.w + off);
        nbox[r] = nb;
        area_s[r] = (nb.z - nb.x) * (nb.w - nb.y);
    }
    __syncthreads();

    // ---- greedy NMS: sorted order => argmax == forward cursor ----
    int cursor = 0;   // only tid 0 uses
    for (int it = 0; it < MAXDET; it++) {
        if (tid == 0) {
            int c = cursor;
            while (c < TOPK && !active[c]) c++;
            cursor = c;
            if (c < TOPK) { keepf[c] = 1; sPick = c; }
            else          sPick = -1;
        }
        __syncthreads();
        int p = sPick;
        if (p < 0) break;
        float4 pb = nbox[p];
        float  pa = area_s[p];
        for (int j = tid; j < TOPK; j += NT) {
            if (active[j]) {
                float4 qb = nbox[j];
                float xx1 = fmaxf(pb.x, qb.x);
                float yy1 = fmaxf(pb.y, qb.y);
                float xx2 = fminf(pb.z, qb.z);
                float yy2 = fminf(pb.w, qb.w);
                float inter = fmaxf(xx2 - xx1, 0.f) * fmaxf(yy2 - yy1, 0.f);
                float iou = inter / (pa + area_s[j] - inter);
                if (!(iou <= IOU_THR)) active[j] = 0;   // NaN-safe, matches jax mask
            }
        }
        __syncthreads();
    }
    __syncthreads();

    // ---- write detections ----
    float* det = dets + (size_t)b * TOPK * 5;
    for (int r = tid; r < TOPK; r += NT) {
        float v0 = 0.f, v1 = 0.f, v2 = 0.f, v3 = 0.f, v4 = 0.f;
        if (keepf[r]) {
            unsigned long long key = keys[2047 - r];
            unsigned int idx = 0xFFFFFFFFu - (unsigned int)key;
            float4 bx = g_boxes[b * NTOT + idx];
            v0 = bx.x; v1 = bx.y; v2 = bx.z; v3 = bx.w;
            v4 = __uint_as_float((unsigned int)(key >> 32));
        }
        det[r*5+0] = v0; det[r*5+1] = v1; det[r*5+2] = v2; det[r*5+3] = v3; det[r*5+4] = v4;
    }
}

// ---------------- launch ----------------------------------------------------
extern "C" void kernel_launch(void* const* d_in, const int* in_sizes, int n_in,
                              void* d_out, int out_size)
{
    const float* l3 = (const float*)d_in[0];
    const float* l4 = (const float*)d_in[1];
    const float* l5 = (const float*)d_in[2];
    const float* gt = (const float*)d_in[3];

    const float *c3, *c4, *c5, *r3, *r4, *r5, *t3, *t4, *t5;
    if (in_sizes[5] == BATCH * N3 * 4) {
        // dict order: cls_p3, reg_p3, ctr_p3, cls_p4, reg_p4, ctr_p4, cls_p5, reg_p5, ctr_p5
        c3 = (const float*)d_in[4];  r3 = (const float*)d_in[5];  t3 = (const float*)d_in[6];
        c4 = (const float*)d_in[7];  r4 = (const float*)d_in[8];  t4 = (const float*)d_in[9];
        c5 = (const float*)d_in[10]; r5 = (const float*)d_in[11]; t5 = (const float*)d_in[12];
    } else {
        // signature order: cls_p3,cls_p4,cls_p5, reg_p3,reg_p4,reg_p5, ctr_p3,ctr_p4,ctr_p5
        c3 = (const float*)d_in[4];  c4 = (const float*)d_in[5];  c5 = (const float*)d_in[6];
        r3 = (const float*)d_in[7];  r4 = (const float*)d_in[8];  r5 = (const float*)d_in[9];
        t3 = (const float*)d_in[10]; t4 = (const float*)d_in[11]; t5 = (const float*)d_in[12];
    }

    float* out       = (float*)d_out;
    float* out_dets  = out;                                        // [16,1000,5]
    float* out_delta = out + (size_t)BATCH * TOPK * 5;             // [16,21504,4]
    float* out_ctr   = out_delta + (size_t)BATCH * NTOT * 4;       // [16,21504]

    dim3 blk(256);
    dim3 grd((NTOT + 255) / 256, BATCH);

    k_targets<<<grd, blk>>>(l3, l4, l5, gt, out_delta, out_ctr);
    k_score  <<<grd, blk>>>(l3, l4, l5, c3, c4, c5, r3, r4, r5, t3, t4, t5);
    k_select <<<BATCH, 1024>>>(out_dets);
}

// round 2
// speedup vs baseline: 1.8733x; 1.8733x over previous
#include <cuda_runtime.h>
#include <math.h>

#define BATCH 16
#define NCLS  20
#define NGT   64
#define N3    16384
#define N4    4096
#define N5    1024
#define NTOT  (N3 + N4 + N5)     // 21504
#define TOPK  1000
#define MAXDET 100
#define SCORE_THR 0.3f
#define IOU_THR   0.5f
#define NBIN  4096
#define TB0   0x3E99999Au        // float bits of 0.3f

// ---------------- scratch (device globals; zero-initialized at load) --------
__device__ float        g_scores[BATCH * NTOT];
__device__ float4       g_boxes [BATCH * NTOT];
__device__ int          g_cls   [BATCH * NTOT];
__device__ unsigned int g_hist  [BATCH * NBIN];   // zeroed by k_select after use

__device__ __forceinline__ float sigmoidf_(float x) {
    if (x >= 0.f) return 1.f / (1.f + expf(-x));
    float e = expf(x);
    return e / (1.f + e);
}
__device__ __forceinline__ unsigned int fenc(float f) {
    unsigned int u = __float_as_uint(f);
    return (u & 0x80000000u) ? ~u : (u | 0x80000000u);
}
__device__ __forceinline__ float fdec(unsigned int e) {
    return (e & 0x80000000u) ? __uint_as_float(e & 0x7FFFFFFFu) : __uint_as_float(~e);
}

// =========== fused kernel: targets + score/decode + score histogram =========
__global__ __launch_bounds__(256) void k_fused(
    const float* __restrict__ l3, const float* __restrict__ l4, const float* __restrict__ l5,
    const float* __restrict__ gt,
    const float* __restrict__ c3, const float* __restrict__ c4, const float* __restrict__ c5,
    const float* __restrict__ r3, const float* __restrict__ r4, const float* __restrict__ r5,
    const float* __restrict__ t3, const float* __restrict__ t4, const float* __restrict__ t5,
    float* __restrict__ od, float* __restrict__ oc)
{
    const int b   = blockIdx.y;
    const int tid = threadIdx.x;
    const int i   = blockIdx.x * 256 + tid;          // 84*256 == NTOT exactly

    __shared__ float4 sbox[NGT];
    __shared__ float  sarea[NGT];
    __shared__ int    swcnt[2];
    __shared__ int    scnt;

    // ---- load + order-preserving compaction of valid GT boxes ----
    float x0 = 0.f, y0 = 0.f, x1 = 0.f, y1 = 0.f;
    bool  val = false;
    int   pref = 0;
    if (tid < 64) {                                   // warps 0,1 fully active
        const float* g = gt + (size_t)b * NGT * 5 + tid * 5;
        x0 = g[0]; y0 = g[1]; x1 = g[2]; y1 = g[3];
        val = (x0 >= 0.f);                            // pads are all -1
        int lane = tid & 31, w = tid >> 5;
        unsigned m = __ballot_sync(0xFFFFFFFFu, val);
        pref = __popc(m & ((1u << lane) - 1));
        if (lane == 0) swcnt[w] = __popc(m);
    }
    __syncthreads();
    if (tid < 64 && val) {
        int base = (tid >= 32) ? swcnt[0] : 0;
        int pos  = base + pref;
        sbox[pos]  = make_float4(x0, y0, x1, y1);
        sarea[pos] = (x1 - x0) * (y1 - y0);
    }
    if (tid == 0) scnt = swcnt[0] + swcnt[1];
    __syncthreads();

    // ---- level params + location ----
    float xc, yc, lower, upper, stride;
    int j, n;
    const float *cls, *reg, *ctr;
    if (i < N3)           { j = i;            n = N3; xc = l3[2*j]; yc = l3[2*j+1]; lower = 0.f;   upper = 64.f;     stride = 8.f;  cls = c3; reg = r3; ctr = t3; }
    else if (i < N3 + N4) { j = i - N3;       n = N4; xc = l4[2*j]; yc = l4[2*j+1]; lower = 64.f;  upper = 128.f;    stride = 16.f; cls = c4; reg = r4; ctr = t4; }
    else                  { j = i - N3 - N4;  n = N5; xc = l5[2*j]; yc = l5[2*j+1]; lower = 128.f; upper = INFINITY; stride = 32.f; cls = c5; reg = r5; ctr = t5; }

    // ---- GT matching: min-area among eligible, first-wins on ties ----
    float bestA = INFINITY;
    int   besti = -1;
    const int nv = scnt;
    for (int m = 0; m < nv; m++) {
        float4 bb = sbox[m];
        float l = xc - bb.x, t = yc - bb.y, r = bb.z - xc, bo = bb.w - yc;
        float mn = fminf(fminf(l, t), fminf(r, bo));
        float mx = fmaxf(fmaxf(l, t), fmaxf(r, bo));
        float a  = sarea[m];
        if (mn > 0.f && mx > lower && mx < upper && a < bestA) { bestA = a; besti = m; }
    }

    float d0, d1, d2, d3, ctrt;
    if (besti < 0) {
        d0 = d1 = d2 = d3 = -1.f; ctrt = -1.f;
    } else {
        float4 bb = sbox[besti];
        d0 = (xc - bb.x) / stride;
        d1 = (yc - bb.y) / stride;
        d2 = (bb.z - xc) / stride;
        d3 = (bb.w - yc) / stride;
        float num = fminf(d0, d2) * fminf(d1, d3);
        float den = fmaxf(d0, d2) * fmaxf(d1, d3);
        ctrt = sqrtf(num / den);
    }
    size_t base = (size_t)(b * NTOT + i);
    od[base*4+0] = d0; od[base*4+1] = d1; od[base*4+2] = d2; od[base*4+3] = d3;
    oc[base] = ctrt;

    // ---- class-max score + decode ----
    const float4* cp4 = reinterpret_cast<const float4*>(cls + ((size_t)b * n + j) * NCLS);
    float best = -INFINITY; int bc = 0;
    #pragma unroll
    for (int c4i = 0; c4i < 5; c4i++) {
        float4 v = cp4[c4i];
        if (v.x > best) { best = v.x; bc = c4i*4+0; }
        if (v.y > best) { best = v.y; bc = c4i*4+1; }
        if (v.z > best) { best = v.z; bc = c4i*4+2; }
        if (v.w > best) { best = v.w; bc = c4i*4+3; }
    }
    float sc = sqrtf(sigmoidf_(best) * sigmoidf_(ctr[(size_t)b * n + j]));

    float4 rp = reinterpret_cast<const float4*>(reg)[(size_t)b * n + j];
    float e0 = fmaxf(rp.x, 0.f) * stride;
    float e1 = fmaxf(rp.y, 0.f) * stride;
    float e2 = fmaxf(rp.z, 0.f) * stride;
    float e3 = fmaxf(rp.w, 0.f) * stride;

    int o = b * NTOT + i;
    g_scores[o] = sc;
    g_boxes[o]  = make_float4(xc - e0, yc - e1, xc + e2, yc + e3);
    g_cls[o]    = bc;

    unsigned int sb = __float_as_uint(sc);
    if (sb > TB0) atomicAdd(&g_hist[b * NBIN + ((sb >> 13) & (NBIN-1))], 1u);
}

// =========== per-batch top-1000 + greedy NMS ================================
__global__ __launch_bounds__(1024) void k_select(float* __restrict__ dets)
{
    __shared__ unsigned long long keys[2048];                 // 16 KB
    __shared__ __align__(16) unsigned char uni[20480];        // union: hist / nbox+areas
    __shared__ unsigned int abits[32];
    __shared__ unsigned char keepf[1024];
    __shared__ unsigned int wsum[32], wAbove[32];
    __shared__ unsigned int sCnt, sMaxU;
    __shared__ int sB, sB2, sTotal, sCand, sAbove;

    unsigned int* shist = (unsigned int*)uni;                 // [4096]
    float4*       nbox  = (float4*)uni;                       // [1000]
    float*        areas = (float*)(uni + 16000);              // [1000]

    const int b    = blockIdx.x;
    const int tid  = threadIdx.x;
    const int lane = tid & 31, wid = tid >> 5;
    const float* sc = g_scores + b * NTOT;

    // ---- phase 1: pull histogram, zero global copy for next replay ----
    for (int k = tid; k < NBIN; k += 1024) {
        unsigned v = g_hist[b * NBIN + k];
        shist[k] = v;
        g_hist[b * NBIN + k] = 0;
    }
    if (tid == 0) { sB = 0; sB2 = 0; sCand = 0; sAbove = 0; sCnt = 0; sMaxU = fenc(0.0f); }
    __syncthreads();

    // ---- phase 2: parallel suffix scan -> threshold bin ----
    unsigned s0 = shist[4*tid], s1 = shist[4*tid+1], s2 = shist[4*tid+2], s3 = shist[4*tid+3];
    unsigned st = s0 + s1 + s2 + s3;
    unsigned inc = st;
    #pragma unroll
    for (int off = 1; off < 32; off <<= 1) {
        unsigned v = __shfl_down_sync(0xFFFFFFFFu, inc, off);
        if (lane + off < 32) inc += v;
    }
    if (lane == 0) wsum[wid] = inc;
    __syncthreads();
    if (tid < 32) {
        unsigned v = wsum[tid], winc = v;
        #pragma unroll
        for (int off = 1; off < 32; off <<= 1) {
            unsigned u = __shfl_down_sync(0xFFFFFFFFu, winc, off);
            if (tid + off < 32) winc += u;
        }
        wAbove[tid] = winc - v;
        if (tid == 0) sTotal = (int)winc;
    }
    __syncthreads();
    {
        unsigned cum = wAbove[wid] + (inc - st);       // strictly above my 4-bin chunk
        unsigned hh[4] = { s3, s2, s1, s0 };
        #pragma unroll
        for (int q = 0; q < 4; q++) {
            if (cum < TOPK && cum + hh[q] >= TOPK) {
                sB = 4*tid + 3 - q; sCand = (int)(cum + hh[q]); sAbove = (int)cum;
            }
            cum += hh[q];
        }
    }
    __syncthreads();
    if (sTotal < TOPK) {               // uniform branch
        if (tid == 0) sCand = sTotal;  // B stays 0: take everything > 0.3
        __syncthreads();
    }
    const int B = sB;
    int B2 = 0;

    // ---- rare refinement: boundary bin too fat for the 2048-key buffer ----
    if (sCand > 2040) {                // uniform branch (data-deterministic)
        for (int k = tid; k < 2048; k += 1024) shist[k] = 0;
        __syncthreads();
        for (int k = tid; k < NTOT; k += 1024) {
            unsigned bits = __float_as_uint(sc[k]);
            if (bits > TB0 && (int)((bits >> 13) & (NBIN-1)) == B)
                atomicAdd(&shist[(bits >> 2) & 2047u], 1u);
        }
        __syncthreads();
        if (tid == 0) {
            unsigned cum2 = (unsigned)sAbove; int bb = 0;
            for (int k = 2047; k >= 0; k--) {
                if (cum2 + shist[k] >= TOPK) { bb = k; break; }
                cum2 += shist[k];
            }
            sB2 = bb;
        }
        __syncthreads();
        B2 = sB2;
    }

    // ---- phase 3: compaction (warp-aggregated) ----
    for (int k = tid; k < NTOT; k += 1024) {
        unsigned bits = __float_as_uint(sc[k]);
        int bin = (int)((bits >> 13) & (NBIN-1));
        bool cand = (bits > TB0) && (bin > B || (bin == B && (int)((bits >> 2) & 2047u) >= B2));
        unsigned m = __ballot_sync(0xFFFFFFFFu, cand);
        int leader = __ffs(m) - 1;
        unsigned base = 0;
        if (cand && lane == leader) base = atomicAdd(&sCnt, (unsigned)__popc(m));
        base = __shfl_sync(0xFFFFFFFFu, base, leader < 0 ? 0 : leader);
        if (cand) {
            unsigned pos = base + __popc(m & ((1u << lane) - 1));
            if (pos < 2048)
                keys[pos] = ((unsigned long long)bits << 32)
                          | (unsigned long long)(0xFFFFFFFFu - (unsigned)k);
        }
    }
    __syncthreads();
    const unsigned S = min(sCnt, 2048u);
    for (int k = tid; k < 2048; k += 1024)
        if ((unsigned)k >= S) keys[k] = 0ull;

    // ---- phase 4: bitonic sort ascending (rank r at keys[2047-r]) ----
    for (unsigned ksz = 2; ksz <= 2048; ksz <<= 1) {
        for (unsigned jj = ksz >> 1; jj > 0; jj >>= 1) {
            __syncthreads();
            for (unsigned idx = tid; idx < 2048; idx += 1024) {
                unsigned ixj = idx ^ jj;
                if (ixj > idx) {
                    unsigned long long a = keys[idx], c = keys[ixj];
                    bool up = ((idx & ksz) == 0);
                    if (up ? (a > c) : (a < c)) { keys[idx] = c; keys[ixj] = a; }
                }
            }
        }
    }
    __syncthreads();

    // ---- phase 5: gather top-1000, max_coord, active bitmap ----
    unsigned long long key = (tid < TOPK) ? keys[2047 - tid] : 0ull;
    float s = __uint_as_float((unsigned)(key >> 32));
    unsigned gidx = 0xFFFFFFFFu - (unsigned)key;
    bool valid = (tid < TOPK) && (key != 0ull);    // compaction filter => s > 0.3 strict
    float4 bx = make_float4(0.f, 0.f, 0.f, 0.f);
    int cid = 0;
    if (valid) { bx = g_boxes[b * NTOT + gidx]; cid = g_cls[b * NTOT + gidx]; }
    keepf[tid] = 0;
    float mrow = valid ? fmaxf(fmaxf(bx.x, bx.y), fmaxf(bx.z, bx.w)) : 0.f;
    atomicMax(&sMaxU, fenc(mrow));
    {
        unsigned am = __ballot_sync(0xFFFFFFFFu, valid);
        if (lane == 0) abits[wid] = am;
    }
    __syncthreads();
    const float offmul = fdec(sMaxU) + 1.0f;
    if (tid < TOPK) {
        float o = (float)cid * offmul;
        float4 nb = make_float4(bx.x + o, bx.y + o, bx.z + o, bx.w + o);
        nbox[tid]  = nb;
        areas[tid] = (nb.z - nb.x) * (nb.w - nb.y);
    }
    __syncthreads();

    // ---- phase 6: greedy NMS, 1 barrier per iteration ----
    int cursor = 0;
    for (int it = 0; it < MAXDET; it++) {
        // all threads redundantly find first active >= cursor
        int p = -1;
        int w = cursor >> 5;
        unsigned m = (w < 32) ? (abits[w] & (0xFFFFFFFFu << (cursor & 31))) : 0u;
        while (w < 32) {
            if (m) { p = (w << 5) + __ffs(m) - 1; break; }
            w++;
            m = (w < 32) ? abits[w] : 0u;
        }
        if (p < 0) break;
        if (tid == 0) keepf[p] = 1;
        cursor = p + 1;
        // sweep: this thread owns element tid
        if (tid >= p && tid < TOPK && ((abits[tid >> 5] >> (tid & 31)) & 1u)) {
            float4 pb = nbox[p];
            float  pa = areas[p];
            float4 qb = nbox[tid];
            float xx1 = fmaxf(pb.x, qb.x);
            float yy1 = fmaxf(pb.y, qb.y);
            float xx2 = fminf(pb.z, qb.z);
            float yy2 = fminf(pb.w, qb.w);
            float inter = fmaxf(xx2 - xx1, 0.f) * fmaxf(yy2 - yy1, 0.f);
            float iou = inter / (pa + areas[tid] - inter);
            if (!(iou <= IOU_THR))                       // NaN-safe, matches jax mask
                atomicAnd(&abits[tid >> 5], ~(1u << (tid & 31)));
        }
        __syncthreads();
    }
    __syncthreads();

    // ---- phase 7: write detections ----
    if (tid < TOPK) {
        float* det = dets + (size_t)b * TOPK * 5 + (size_t)tid * 5;
        if (keepf[tid]) {
            det[0] = bx.x; det[1] = bx.y; det[2] = bx.z; det[3] = bx.w; det[4] = s;
        } else {
            det[0] = 0.f; det[1] = 0.f; det[2] = 0.f; det[3] = 0.f; det[4] = 0.f;
        }
    }
}

// ---------------- launch ----------------------------------------------------
extern "C" void kernel_launch(void* const* d_in, const int* in_sizes, int n_in,
                              void* d_out, int out_size)
{
    const float* l3 = (const float*)d_in[0];
    const float* l4 = (const float*)d_in[1];
    const float* l5 = (const float*)d_in[2];
    const float* gt = (const float*)d_in[3];

    const float *c3, *c4, *c5, *r3, *r4, *r5, *t3, *t4, *t5;
    if (in_sizes[5] == BATCH * N3 * 4) {
        c3 = (const float*)d_in[4];  r3 = (const float*)d_in[5];  t3 = (const float*)d_in[6];
        c4 = (const float*)d_in[7];  r4 = (const float*)d_in[8];  t4 = (const float*)d_in[9];
        c5 = (const float*)d_in[10]; r5 = (const float*)d_in[11]; t5 = (const float*)d_in[12];
    } else {
        c3 = (const float*)d_in[4];  c4 = (const float*)d_in[5];  c5 = (const float*)d_in[6];
        r3 = (const float*)d_in[7];  r4 = (const float*)d_in[8];  r5 = (const float*)d_in[9];
        t3 = (const float*)d_in[10]; t4 = (const float*)d_in[11]; t5 = (const float*)d_in[12];
    }

    float* out       = (float*)d_out;
    float* out_dets  = out;                                   // [16,1000,5]
    float* out_delta = out + (size_t)BATCH * TOPK * 5;        // [16,21504,4]
    float* out_ctr   = out_delta + (size_t)BATCH * NTOT * 4;  // [16,21504]

    dim3 grd(NTOT / 256, BATCH);
    k_fused <<<grd, 256>>>(l3, l4, l5, gt, c3, c4, c5, r3, r4, r5, t3, t4, t5,
                           out_delta, out_ctr);
    k_select<<<BATCH, 1024>>>(out_dets);
}